// round 16
// baseline (speedup 1.0000x reference)
#include <cuda_runtime.h>
#include <cuda_fp16.h>

#define HID  51
#define TT   2048
#define NN   1024
#define NSEQ 8
#define NTH  128          // 4 warps; 8 sequences per block; grid = 128
#define HSTR 66           // H row stride in halfs (bank stagger)

__device__ __forceinline__ float tanhx(float x) {
    float r; asm("tanh.approx.f32 %0, %1;" : "=f"(r) : "f"(x)); return r;
}
__device__ __forceinline__ float sg(float x) {          // sigmoid via tanh
    return fmaf(0.5f, tanhx(0.5f * x), 0.5f);
}
__device__ __forceinline__ unsigned packh2(float a, float b) {
    __half2 h = __floats2half2_rn(a, b);
    return *(unsigned*)&h;
}
__device__ __forceinline__ void mma16816(float c[4], const unsigned a[4],
                                         const unsigned b[2]) {
    asm volatile(
        "mma.sync.aligned.m16n8k16.row.col.f32.f16.f16.f32 "
        "{%0,%1,%2,%3}, {%4,%5,%6,%7}, {%8,%9}, {%0,%1,%2,%3};"
        : "+f"(c[0]), "+f"(c[1]), "+f"(c[2]), "+f"(c[3])
        : "r"(a[0]), "r"(a[1]), "r"(a[2]), "r"(a[3]), "r"(b[0]), "r"(b[1]));
}

// W element for gate-row r (r = u*4+g, u=51 -> layer-2), k in [0,64)
__device__ float w_elem(int r, int k,
                        const float* Whh1, const float* Wih1,
                        const float* bih1, const float* bhh1,
                        const float* Wih2, const float* Whh2,
                        const float* bih2, const float* bhh2) {
    if (r < 204) {
        int u = r >> 2, g = r & 3;
        int tr = g * HID + u;
        if (k < HID)  return Whh1[tr * HID + k];
        if (k == 51)  return Wih1[tr];
        if (k == 52)  return bih1[tr] + bhh1[tr];
        return 0.f;
    } else {
        int g = r - 204;
        if (k < HID)  return Wih2[g * HID + k];
        if (k == 52)  return bih2[g] + bhh2[g];
        if (k == 53)  return Whh2[g];
        return 0.f;
    }
}

__global__ void __launch_bounds__(NTH)
lstm2_kernel(const float* __restrict__ stim,
             const float* __restrict__ Wih1,
             const float* __restrict__ Whh1,
             const float* __restrict__ bih1,
             const float* __restrict__ bhh1,
             const float* __restrict__ Wih2,
             const float* __restrict__ Whh2,
             const float* __restrict__ bih2,
             const float* __restrict__ bhh2,
             float* __restrict__ out)
{
    __shared__ __align__(16) __half H[NSEQ][HSTR];     // B operand [seq][k]; k=51:x, 52:1, 53:h2
    __shared__ __align__(16) float gateC[52 * 8 * 4];  // [u][seq][gate]
    __shared__ __align__(16) float x_sh[2][NSEQ][64];
    __shared__ __align__(16) float ob_sh[NSEQ][64];

    const int tid = threadIdx.x;
    const int w   = tid >> 5;
    const int l   = tid & 31;
    const int n0  = blockIdx.x * NSEQ;

    // ---- A fragments: warp w owns m-tiles {w, w+4, w+8} (+tile 12 for w==0)
    const int NT = (w == 0) ? 4 : 3;
    unsigned afr[4][4][4];
#pragma unroll
    for (int i = 0; i < 4; i++)
#pragma unroll
        for (int kt = 0; kt < 4; kt++)
#pragma unroll
            for (int j = 0; j < 4; j++) afr[i][kt][j] = 0u;
#pragma unroll
    for (int i = 0; i < 4; i++) {
        if (i < NT) {
            int gt = w + 4 * i;
            int r0 = 16 * gt + (l >> 2);
            int k0 = (l & 3) * 2;
#pragma unroll
            for (int kt = 0; kt < 4; kt++) {
                int kb = 16 * kt + k0;
                afr[i][kt][0] = packh2(
                    w_elem(r0,     kb,     Whh1, Wih1, bih1, bhh1, Wih2, Whh2, bih2, bhh2),
                    w_elem(r0,     kb + 1, Whh1, Wih1, bih1, bhh1, Wih2, Whh2, bih2, bhh2));
                afr[i][kt][1] = packh2(
                    w_elem(r0 + 8, kb,     Whh1, Wih1, bih1, bhh1, Wih2, Whh2, bih2, bhh2),
                    w_elem(r0 + 8, kb + 1, Whh1, Wih1, bih1, bhh1, Wih2, Whh2, bih2, bhh2));
                afr[i][kt][2] = packh2(
                    w_elem(r0,     kb + 8, Whh1, Wih1, bih1, bhh1, Wih2, Whh2, bih2, bhh2),
                    w_elem(r0,     kb + 9, Whh1, Wih1, bih1, bhh1, Wih2, Whh2, bih2, bhh2));
                afr[i][kt][3] = packh2(
                    w_elem(r0 + 8, kb + 8, Whh1, Wih1, bih1, bhh1, Wih2, Whh2, bih2, bhh2),
                    w_elem(r0 + 8, kb + 9, Whh1, Wih1, bih1, bhh1, Wih2, Whh2, bih2, bhh2));
            }
        }
    }
    const int scat_r0 = 16 * (w)     ;   // recomputed per tile below

    // ---- owner pairs: p0..p2 = tid+128i (all); p3 = tid+288 (tid>=96) ----
    const bool hasP3 = (tid >= 96);
    const int  p3    = tid + 288;                 // 384..415
    const bool isl2  = (p3 >> 3) == HID && hasP3; // tid 120..127
    const int  seqL2 = p3 & 7;
    float cst[4] = {0.f, 0.f, 0.f, 0.f};

    // ---- init shared ----------------------------------------------------
    for (int i = tid; i < (int)(sizeof(H) / 4); i += NTH) ((unsigned*)H)[i] = 0u;
    {
        int seq = tid >> 4, q = (tid & 15) * 4;
        *(float4*)&x_sh[0][seq][q] = *(const float4*)&stim[(n0 + seq) * TT + q];
    }
    __syncthreads();
    if (tid < NSEQ) {
        H[tid][52] = __float2half_rn(1.0f);
        H[tid][51] = __float2half_rn(x_sh[0][tid][0]);
    }
    __syncthreads();

    float4 xstage = make_float4(0.f, 0.f, 0.f, 0.f);

#pragma unroll 1
    for (int t = 0; t < TT; t++) {
        // ============ MMA phase ============
        unsigned bfr[4][2];
        {
            const __half* hrow = &H[l >> 2][0];
            const int kof = (l & 3) * 2;
#pragma unroll
            for (int kt = 0; kt < 4; kt++) {
                bfr[kt][0] = *(const unsigned*)&hrow[16 * kt + kof];
                bfr[kt][1] = *(const unsigned*)&hrow[16 * kt + kof + 8];
            }
        }
        float cfr[4][4];
#pragma unroll
        for (int i = 0; i < 4; i++)
#pragma unroll
            for (int j = 0; j < 4; j++) cfr[i][j] = 0.f;
#pragma unroll
        for (int i = 0; i < 4; i++) {
            if (i < NT) {
#pragma unroll
                for (int kt = 0; kt < 4; kt++)
                    mma16816(cfr[i], afr[i][kt], bfr[kt]);
            }
        }
        // scatter C -> gateC[u][seq][gate]
#pragma unroll
        for (int i = 0; i < 4; i++) {
            if (i < NT) {
                int gt = w + 4 * i;
                int r0 = 16 * gt + (l >> 2);
                int nn = (l & 3) * 2;
                int idx = (r0 >> 2) * 32 + nn * 4 + (r0 & 3);
                gateC[idx]      = cfr[i][0];
                gateC[idx + 4]  = cfr[i][1];
                gateC[idx + 64] = cfr[i][2];
                gateC[idx + 68] = cfr[i][3];
            }
        }
        __syncthreads();

        // ============ owner phase ============
#pragma unroll
        for (int i = 0; i < 3; i++) {
            int p = tid + 128 * i;
            float4 gv = *(const float4*)&gateC[p * 4];
            int u = p >> 3, seq = p & 7;
            cst[i] = fmaf(sg(gv.y), cst[i], sg(gv.x) * tanhx(gv.z));
            H[seq][u] = __float2half_rn(sg(gv.w) * tanhx(cst[i]));
        }
        if (hasP3) {
            if (!isl2) {
                float4 gv = *(const float4*)&gateC[p3 * 4];
                int u = p3 >> 3, seq = p3 & 7;
                cst[3] = fmaf(sg(gv.y), cst[3], sg(gv.x) * tanhx(gv.z));
                H[seq][u] = __float2half_rn(sg(gv.w) * tanhx(cst[3]));
            } else {
                if (t > 0) {
                    float4 gv = *(const float4*)&gateC[p3 * 4];
                    cst[3] = fmaf(sg(gv.y), cst[3], sg(gv.x) * tanhx(gv.z));
                    float y = sg(gv.w) * tanhx(cst[3]);
                    ob_sh[seqL2][(t - 1) & 63] = y;
                    H[seqL2][53] = __float2half_rn(y);
                }
                if (t + 1 < TT) {
                    float xn = x_sh[((t + 1) >> 6) & 1][seqL2][(t + 1) & 63];
                    H[seqL2][51] = __float2half_rn(xn);
                }
            }
        }

        const int dt = t & 63;
        if (dt == 0) {
            __syncthreads();               // slot-63 write visible to flushers
            int seq = tid >> 4, q = (tid & 15) * 4;
            if (t > 0)
                *(float4*)&out[(n0 + seq) * TT + (t - 64) + q] =
                    *(const float4*)&ob_sh[seq][q];
            if (t + 64 < TT)
                xstage = *(const float4*)&stim[(n0 + seq) * TT + t + 64 + q];
        }
        if (dt == 32 && t + 32 < TT) {
            int seq = tid >> 4, q = (tid & 15) * 4;
            *(float4*)&x_sh[((t >> 6) + 1) & 1][seq][q] = xstage;
        }
        __syncthreads();
    }

    // ---- tail: y(2047) = layer2(h1(2047), h2(2046)) ---------------------
    if (isl2) {
        float h2v = __half2float(H[seqL2][53]);
        float gt4[4] = {0.f, 0.f, 0.f, 0.f};
        for (int k = 0; k < HID; k++) {
            float hv = __half2float(H[seqL2][k]);
#pragma unroll
            for (int g = 0; g < 4; g++)
                gt4[g] = fmaf(Wih2[g * HID + k], hv, gt4[g]);
        }
#pragma unroll
        for (int g = 0; g < 4; g++)
            gt4[g] += fmaf(Whh2[g], h2v, bih2[g] + bhh2[g]);
        cst[3] = fmaf(sg(gt4[1]), cst[3], sg(gt4[0]) * tanhx(gt4[2]));
        ob_sh[seqL2][63] = sg(gt4[3]) * tanhx(cst[3]);
    }
    __syncthreads();
    {
        int seq = tid >> 4, q = (tid & 15) * 4;
        *(float4*)&out[(n0 + seq) * TT + (TT - 64) + q] =
            *(const float4*)&ob_sh[seq][q];
    }
}

extern "C" void kernel_launch(void* const* d_in, const int* in_sizes, int n_in,
                              void* d_out, int out_size)
{
    (void)in_sizes; (void)n_in; (void)out_size;
    const float* stim  = (const float*)d_in[0];
    const float* Wih1  = (const float*)d_in[1];
    const float* Whh1  = (const float*)d_in[2];
    const float* bih1  = (const float*)d_in[3];
    const float* bhh1  = (const float*)d_in[4];
    const float* Wih2  = (const float*)d_in[5];
    const float* Whh2  = (const float*)d_in[6];
    const float* bih2  = (const float*)d_in[7];
    const float* bhh2  = (const float*)d_in[8];
    float* out = (float*)d_out;

    lstm2_kernel<<<NN / NSEQ, NTH>>>(stim, Wih1, Whh1, bih1, bhh1,
                                     Wih2, Whh2, bih2, bhh2, out);
}

// round 17
// speedup vs baseline: 1.7526x; 1.7526x over previous
#include <cuda_runtime.h>
#include <cuda_fp16.h>

#define HID   51
#define TT    2048
#define NN    1024
#define CHUNK 64
#define NROWS 208         // 204 layer-1 gate rows + 4 layer-2 rows; r = u*4+g
#define NTH   32          // ONE warp per block, one sequence per block

__device__ __forceinline__ float tanhx(float x) {
    float r; asm("tanh.approx.f32 %0, %1;" : "=f"(r) : "f"(x)); return r;
}
__device__ __forceinline__ __half hsum2(__half2 v) {
    return __hadd(__low2half(v), __high2half(v));
}

__global__ void __launch_bounds__(NTH)
lstm2_kernel(const float* __restrict__ stim,
             const float* __restrict__ Wih1,   // (204,1)
             const float* __restrict__ Whh1,   // (204,51)
             const float* __restrict__ bih1,
             const float* __restrict__ bhh1,
             const float* __restrict__ Wih2,   // (4,51)
             const float* __restrict__ Whh2,   // (4,1)
             const float* __restrict__ bih2,
             const float* __restrict__ bhh2,
             float* __restrict__ out)          // (1024,2048)
{
    __shared__ __align__(16) __half hbuf[2][56];   // h1 fp16; [51..55] zero pad
    __shared__ __align__(16) float gaccf[NROWS];   // gate matvec sums (unit-major)
    __shared__ __align__(16) float x_sh[CHUNK];
    __shared__ __align__(16) float ob_sh[CHUNK];   // y(t0+dt-1)

    const int l  = threadIdx.x;
    const int n0 = blockIdx.x;

    // ---- balanced matvec rows: lane l owns rows l+32i (i=0..6, r<208) ---
    __half2 wf[7][26];
#pragma unroll
    for (int i = 0; i < 7; i++)
#pragma unroll
        for (int kk = 0; kk < 26; kk++) wf[i][kk] = __half2half2(__ushort_as_half(0));
#pragma unroll
    for (int i = 0; i < 7; i++) {
        int r = l + 32 * i;
        if (r < NROWS) {
            int u = r >> 2, g = r & 3;
            const float* src = (u < HID) ? (Whh1 + (g * HID + u) * HID)
                                         : (Wih2 + g * HID);
#pragma unroll
            for (int kk = 0; kk < 26; kk++) {
                float a = src[2*kk];
                float b = (2*kk + 1 < HID) ? src[2*kk + 1] : 0.f;
                wf[i][kk] = __floats2half2_rn(a, b);
            }
        }
    }

    // ---- owner lanes: unit A = l; unit B = l+32 (l<19) or layer-2 (l==19)
    const int  uA   = l;
    const int  uB   = l + 32;
    const bool hasB = (l < 20);
    const bool isl2 = (l == 19);
    float biasA[4], wiA[4], biasB[4], wiB[4];
#pragma unroll
    for (int g = 0; g < 4; g++) {
        const int rowA = g * HID + uA;
        biasA[g] = bih1[rowA] + bhh1[rowA];
        wiA[g]   = Wih1[rowA];
        if (l < 19) {
            const int rowB = g * HID + uB;
            biasB[g] = bih1[rowB] + bhh1[rowB];
            wiB[g]   = Wih1[rowB];
        } else if (isl2) {
            biasB[g] = bih2[g] + bhh2[g];
            wiB[g]   = Whh2[g];
        } else { biasB[g] = 0.f; wiB[g] = 0.f; }
    }

    for (int i = l; i < 56; i += NTH) ((unsigned*)hbuf)[i] = 0u;
    float cA = 0.f, cB = 0.f;          // fp32 cell states
    float h2 = 0.f;                    // layer-2 hidden (lane 19)

    if (l < 16)
        *(float4*)&x_sh[l * 4] = *(const float4*)&stim[n0 * TT + l * 4];
    __syncwarp();

#pragma unroll 1
    for (int t0 = 0; t0 < TT; t0 += CHUNK) {
#pragma unroll 2
        for (int dt = 0; dt < CHUNK; dt++) {
            const int rd = dt & 1;
            // ---- balanced matvec: 182 HFMA2, h consumed inline ---------
            __half2 z = __half2half2(__ushort_as_half(0));
            __half2 acc[7] = {z, z, z, z, z, z, z};
            const uint4* h4 = (const uint4*)&hbuf[rd][0];
#pragma unroll
            for (int q = 0; q < 6; q++) {          // k-pairs 0..23
                uint4 v = h4[q];
                __half2 p0 = *(__half2*)&v.x, p1 = *(__half2*)&v.y;
                __half2 p2 = *(__half2*)&v.z, p3 = *(__half2*)&v.w;
#pragma unroll
                for (int i = 0; i < 7; i++) {
                    acc[i] = __hfma2(wf[i][4*q + 0], p0, acc[i]);
                    acc[i] = __hfma2(wf[i][4*q + 1], p1, acc[i]);
                    acc[i] = __hfma2(wf[i][4*q + 2], p2, acc[i]);
                    acc[i] = __hfma2(wf[i][4*q + 3], p3, acc[i]);
                }
            }
            {                                       // k-pairs 24,25
                uint2 v = ((const uint2*)h4)[12];
                __half2 p0 = *(__half2*)&v.x, p1 = *(__half2*)&v.y;
#pragma unroll
                for (int i = 0; i < 7; i++) {
                    acc[i] = __hfma2(wf[i][24], p0, acc[i]);
                    acc[i] = __hfma2(wf[i][25], p1, acc[i]);
                }
            }
            // ---- scatter row sums (fp32) to unit-major slots -----------
#pragma unroll
            for (int i = 0; i < 7; i++) {
                int r = l + 32 * i;
                if (r < NROWS)
                    gaccf[r] = __half2float(hsum2(acc[i]));
            }
            __syncwarp();

            // ---- owner phase: fp32 gate finish + cell update -----------
            const float xt = x_sh[dt];
            {   // unit A (all 32 lanes)
                float4 ga = *(const float4*)&gaccf[uA * 4];
                float i0 = ga.x + fmaf(wiA[0], xt, biasA[0]);
                float f0 = ga.y + fmaf(wiA[1], xt, biasA[1]);
                float g0 = ga.z + fmaf(wiA[2], xt, biasA[2]);
                float o0 = ga.w + fmaf(wiA[3], xt, biasA[3]);
                cA = fmaf(fmaf(0.5f, tanhx(0.5f * f0), 0.5f), cA,
                          fmaf(0.5f, tanhx(0.5f * i0), 0.5f) * tanhx(g0));
                hbuf[1 - rd][uA] =
                    __float2half_rn(fmaf(0.5f, tanhx(0.5f * o0), 0.5f) * tanhx(cA));
            }
            if (hasB) {   // unit B (l<19) or layer-2 (l==19)
                float4 gb = *(const float4*)&gaccf[uB * 4];
                float xb = isl2 ? h2 : xt;
                float i0 = gb.x + fmaf(wiB[0], xb, biasB[0]);
                float f0 = gb.y + fmaf(wiB[1], xb, biasB[1]);
                float g0 = gb.z + fmaf(wiB[2], xb, biasB[2]);
                float o0 = gb.w + fmaf(wiB[3], xb, biasB[3]);
                if (!isl2) {
                    cB = fmaf(fmaf(0.5f, tanhx(0.5f * f0), 0.5f), cB,
                              fmaf(0.5f, tanhx(0.5f * i0), 0.5f) * tanhx(g0));
                    hbuf[1 - rd][uB] =
                        __float2half_rn(fmaf(0.5f, tanhx(0.5f * o0), 0.5f) * tanhx(cB));
                } else if ((t0 | dt) != 0) {       // lag-1 layer-2; skip t=0
                    cB = fmaf(fmaf(0.5f, tanhx(0.5f * f0), 0.5f), cB,
                              fmaf(0.5f, tanhx(0.5f * i0), 0.5f) * tanhx(g0));
                    float y = fmaf(0.5f, tanhx(0.5f * o0), 0.5f) * tanhx(cB);
                    ob_sh[dt] = y;
                    h2 = y;
                }
            }
            __syncwarp();
        }
        // ---- flush outputs (lagged by 1) + stage next chunk ------------
        for (int i = l; i < CHUNK; i += NTH) {
            int t = t0 - 1 + i;
            if (t >= 0) out[n0 * TT + t] = ob_sh[i];
        }
        if (t0 + CHUNK < TT && l < 16)
            *(float4*)&x_sh[l * 4] =
                *(const float4*)&stim[n0 * TT + t0 + CHUNK + l * 4];
        __syncwarp();
    }

    // ---- tail: y(2047) from h1(2047) (in hbuf[0]); lane 19 scalar ------
    if (isl2) {
        float gt[4] = {0.f, 0.f, 0.f, 0.f};
        for (int k = 0; k < HID; k++) {
            float hv = __half2float(hbuf[0][k]);
#pragma unroll
            for (int g = 0; g < 4; g++)
                gt[g] = fmaf(Wih2[g * HID + k], hv, gt[g]);
        }
#pragma unroll
        for (int g = 0; g < 4; g++)
            gt[g] += fmaf(wiB[g], h2, biasB[g]);
        cB = fmaf(fmaf(0.5f, tanhx(0.5f * gt[1]), 0.5f), cB,
                  fmaf(0.5f, tanhx(0.5f * gt[0]), 0.5f) * tanhx(gt[2]));
        out[n0 * TT + (TT - 1)] =
            fmaf(0.5f, tanhx(0.5f * gt[3]), 0.5f) * tanhx(cB);
    }
}

extern "C" void kernel_launch(void* const* d_in, const int* in_sizes, int n_in,
                              void* d_out, int out_size)
{
    (void)in_sizes; (void)n_in; (void)out_size;
    const float* stim  = (const float*)d_in[0];
    const float* Wih1  = (const float*)d_in[1];
    const float* Whh1  = (const float*)d_in[2];
    const float* bih1  = (const float*)d_in[3];
    const float* bhh1  = (const float*)d_in[4];
    const float* Wih2  = (const float*)d_in[5];
    const float* Whh2  = (const float*)d_in[6];
    const float* bih2  = (const float*)d_in[7];
    const float* bhh2  = (const float*)d_in[8];
    float* out = (float*)d_out;

    lstm2_kernel<<<NN, NTH>>>(stim, Wih1, Whh1, bih1, bhh1,
                              Wih2, Whh2, bih2, bhh2, out);
}